// round 6
// baseline (speedup 1.0000x reference)
#include <cuda_runtime.h>
#include <cuda_bf16.h>
#include <math.h>

#define N_NODES 50000
#define DIM     64
#define NHEAD   8
#define NEDGE   800000
#define NEG_SLOPE 0.2f

#define SCAN_BLK  1024
#define SCAN_NBLK ((N_NODES + SCAN_BLK - 1) / SCAN_BLK)   // 49

// Scratch (device globals: allocation-free rule).
// INVARIANT: g_deg and g_flag are zero at module load and re-zeroed by
// fill_kernel each call, so every kernel_launch sees them zeroed.
__device__ float g_sdst[N_NODES * NHEAD];
__device__ float g_ssrc[N_NODES * NHEAD];
__device__ int   g_deg[N_NODES];
__device__ int   g_row[N_NODES + 1];
__device__ int   g_cursor[N_NODES];
__device__ int   g_csr_src[NEDGE];
__device__ volatile int g_incl[SCAN_NBLK];
__device__ volatile int g_flag[SCAN_NBLK];

__device__ __forceinline__ float lrelu(float v) {
    return v >= 0.0f ? v : NEG_SLOPE * v;
}

// ---------------------------------------------------------------------------
// Kernel 1: per-node scores + fused degree histogram.
// Grid covers N_NODES*16 == NEDGE threads exactly.
__global__ void scores_hist_kernel(const float* __restrict__ h_t,
                                   const float* __restrict__ att,
                                   const int* __restrict__ ei) {
    __shared__ float s_att[NHEAD * 2 * DIM];
    for (int i = threadIdx.x; i < NHEAD * 2 * DIM; i += blockDim.x)
        s_att[i] = att[i];
    __syncthreads();

    int idx = blockIdx.x * blockDim.x + threadIdx.x;
    if (idx >= NEDGE) return;

    // histogram part (g_deg pre-zeroed by previous call / module load)
    atomicAdd(&g_deg[ei[NEDGE + idx]], 1);

    // scores part
    int n = idx >> 4;
    int c = idx & 15;
    int h = c & 7;
    bool is_src = (c >= 8);

    const float* arow = s_att + h * (2 * DIM) + (is_src ? DIM : 0);
    const float4* hp = (const float4*)(h_t + (size_t)n * DIM);

    float acc = 0.0f;
#pragma unroll
    for (int k = 0; k < 16; k++) {
        float4 v = hp[k];
        acc += v.x * arow[k * 4 + 0] + v.y * arow[k * 4 + 1]
             + v.z * arow[k * 4 + 2] + v.w * arow[k * 4 + 3];
    }
    if (is_src) g_ssrc[n * NHEAD + h] = acc;
    else        g_sdst[n * NHEAD + h] = acc;
}

// ---------------------------------------------------------------------------
// Kernel 2: single-pass chained scan (49 blocks x 1024). Produces row/cursor.
__global__ void scan_kernel() {
    __shared__ int warp_part[32];
    __shared__ int s_prev;
    int t = threadIdx.x;
    int bid = blockIdx.x;
    int i = bid * SCAN_BLK + t;
    int d = (i < N_NODES) ? g_deg[i] : 0;

    // intra-warp inclusive scan
    int v = d;
#pragma unroll
    for (int o = 1; o < 32; o <<= 1) {
        int u = __shfl_up_sync(0xffffffffu, v, o);
        if ((t & 31) >= o) v += u;
    }
    if ((t & 31) == 31) warp_part[t >> 5] = v;
    __syncthreads();
    if (t < 32) {
        int w = warp_part[t];
#pragma unroll
        for (int o = 1; o < 32; o <<= 1) {
            int u = __shfl_up_sync(0xffffffffu, w, o);
            if (t >= o) w += u;
        }
        warp_part[t] = w;
    }
    __syncthreads();
    int incl = v + ((t >= 32) ? warp_part[(t >> 5) - 1] : 0);  // block-inclusive
    int block_total = warp_part[31];

    // chained prefix across blocks
    if (t == 0) {
        int prev = 0;
        if (bid > 0) {
            while (g_flag[bid - 1] == 0) { }
            prev = g_incl[bid - 1];
        }
        g_incl[bid] = prev + block_total;
        __threadfence();
        g_flag[bid] = 1;
        s_prev = prev;
    }
    __syncthreads();

    if (i < N_NODES) {
        int excl = s_prev + incl - d;
        g_row[i] = excl;
        g_cursor[i] = excl;
    }
    if (i == N_NODES - 1) g_row[N_NODES] = NEDGE;
}

// ---------------------------------------------------------------------------
// Kernel 3: fill CSR; also re-zero g_deg / g_flag for the next call.
__global__ void fill_kernel(const int* __restrict__ ei) {
    int e = blockIdx.x * blockDim.x + threadIdx.x;
    if (e < N_NODES) g_deg[e] = 0;
    if (e < SCAN_NBLK) g_flag[e] = 0;
    if (e >= NEDGE) return;
    int src = ei[e];
    int dst = ei[NEDGE + e];
    int p = atomicAdd(&g_cursor[dst], 1);
    g_csr_src[p] = src;
}

// ---------------------------------------------------------------------------
// Kernel 4: fused softmax + aggregation + ELU (profiled by ncu: launch #4).
// One warp per node; lane -> h = lane>>2, dq = lane&3. 4-way unrolled.
__global__ void node_agg_kernel(const float* __restrict__ h_t,
                                float* __restrict__ out) {
    int warp = (blockIdx.x * blockDim.x + threadIdx.x) >> 5;
    if (warp >= N_NODES) return;
    int lane = threadIdx.x & 31;
    int n = warp;
    int rs = g_row[n];
    int re = g_row[n + 1];

    int h  = lane >> 2;
    int dq = lane & 3;
    float sd = g_sdst[n * NHEAD + h];

    float4 a0 = make_float4(0.f, 0.f, 0.f, 0.f);
    float4 a1 = a0, a2 = a0, a3 = a0;
    float denom = 0.0f;

    for (int base = rs; base < re; base += 32) {
        int cnt = re - base; if (cnt > 32) cnt = 32;
        int s = (lane < cnt) ? g_csr_src[base + lane] : 0;

        int j = 0;
        for (; j + 4 <= cnt; j += 4) {
            int s0 = __shfl_sync(0xffffffffu, s, j);
            int s1 = __shfl_sync(0xffffffffu, s, j + 1);
            int s2 = __shfl_sync(0xffffffffu, s, j + 2);
            int s3 = __shfl_sync(0xffffffffu, s, j + 3);

            float v0 = __ldg(&g_ssrc[s0 * NHEAD + h]);
            float v1 = __ldg(&g_ssrc[s1 * NHEAD + h]);
            float v2 = __ldg(&g_ssrc[s2 * NHEAD + h]);
            float v3 = __ldg(&g_ssrc[s3 * NHEAD + h]);

            const float4* p0 = (const float4*)(h_t + (size_t)s0 * DIM) + dq * 4;
            const float4* p1 = (const float4*)(h_t + (size_t)s1 * DIM) + dq * 4;
            const float4* p2 = (const float4*)(h_t + (size_t)s2 * DIM) + dq * 4;
            const float4* p3 = (const float4*)(h_t + (size_t)s3 * DIM) + dq * 4;
            float4 x00 = p0[0], x01 = p0[1], x02 = p0[2], x03 = p0[3];
            float4 x10 = p1[0], x11 = p1[1], x12 = p1[2], x13 = p1[3];
            float4 x20 = p2[0], x21 = p2[1], x22 = p2[2], x23 = p2[3];
            float4 x30 = p3[0], x31 = p3[1], x32 = p3[2], x33 = p3[3];

            float e0 = __expf(lrelu(sd + v0));
            float e1 = __expf(lrelu(sd + v1));
            float e2 = __expf(lrelu(sd + v2));
            float e3 = __expf(lrelu(sd + v3));
            denom += (e0 + e1) + (e2 + e3);

            a0.x += e0*x00.x; a0.y += e0*x00.y; a0.z += e0*x00.z; a0.w += e0*x00.w;
            a1.x += e0*x01.x; a1.y += e0*x01.y; a1.z += e0*x01.z; a1.w += e0*x01.w;
            a2.x += e0*x02.x; a2.y += e0*x02.y; a2.z += e0*x02.z; a2.w += e0*x02.w;
            a3.x += e0*x03.x; a3.y += e0*x03.y; a3.z += e0*x03.z; a3.w += e0*x03.w;

            a0.x += e1*x10.x; a0.y += e1*x10.y; a0.z += e1*x10.z; a0.w += e1*x10.w;
            a1.x += e1*x11.x; a1.y += e1*x11.y; a1.z += e1*x11.z; a1.w += e1*x11.w;
            a2.x += e1*x12.x; a2.y += e1*x12.y; a2.z += e1*x12.z; a2.w += e1*x12.w;
            a3.x += e1*x13.x; a3.y += e1*x13.y; a3.z += e1*x13.z; a3.w += e1*x13.w;

            a0.x += e2*x20.x; a0.y += e2*x20.y; a0.z += e2*x20.z; a0.w += e2*x20.w;
            a1.x += e2*x21.x; a1.y += e2*x21.y; a1.z += e2*x21.z; a1.w += e2*x21.w;
            a2.x += e2*x22.x; a2.y += e2*x22.y; a2.z += e2*x22.z; a2.w += e2*x22.w;
            a3.x += e2*x23.x; a3.y += e2*x23.y; a3.z += e2*x23.z; a3.w += e2*x23.w;

            a0.x += e3*x30.x; a0.y += e3*x30.y; a0.z += e3*x30.z; a0.w += e3*x30.w;
            a1.x += e3*x31.x; a1.y += e3*x31.y; a1.z += e3*x31.z; a1.w += e3*x31.w;
            a2.x += e3*x32.x; a2.y += e3*x32.y; a2.z += e3*x32.z; a2.w += e3*x32.w;
            a3.x += e3*x33.x; a3.y += e3*x33.y; a3.z += e3*x33.z; a3.w += e3*x33.w;
        }
        for (; j < cnt; j++) {
            int sj = __shfl_sync(0xffffffffu, s, j);
            float ex = __expf(lrelu(sd + __ldg(&g_ssrc[sj * NHEAD + h])));
            denom += ex;
            const float4* hp = (const float4*)(h_t + (size_t)sj * DIM) + dq * 4;
            float4 x0 = hp[0], x1 = hp[1], x2 = hp[2], x3 = hp[3];
            a0.x += ex*x0.x; a0.y += ex*x0.y; a0.z += ex*x0.z; a0.w += ex*x0.w;
            a1.x += ex*x1.x; a1.y += ex*x1.y; a1.z += ex*x1.z; a1.w += ex*x1.w;
            a2.x += ex*x2.x; a2.y += ex*x2.y; a2.z += ex*x2.z; a2.w += ex*x2.w;
            a3.x += ex*x3.x; a3.y += ex*x3.y; a3.z += ex*x3.z; a3.w += ex*x3.w;
        }
    }

    float inv = (re > rs) ? 1.0f / denom : 0.0f;   // zero-degree -> zeros

    float4* op = (float4*)(out + (size_t)n * (NHEAD * DIM) + h * DIM + dq * 16);
    float4 r[4] = {a0, a1, a2, a3};
#pragma unroll
    for (int k = 0; k < 4; k++) {
        float4 x = r[k];
        x.x *= inv; x.y *= inv; x.z *= inv; x.w *= inv;
        x.x = x.x > 0.f ? x.x : expm1f(x.x);
        x.y = x.y > 0.f ? x.y : expm1f(x.y);
        x.z = x.z > 0.f ? x.z : expm1f(x.z);
        x.w = x.w > 0.f ? x.w : expm1f(x.w);
        op[k] = x;
    }
}

// ---------------------------------------------------------------------------
extern "C" void kernel_launch(void* const* d_in, const int* in_sizes, int n_in,
                              void* d_out, int out_size) {
    const float* h_t = (const float*)d_in[0];
    const int*   ei  = (const int*)d_in[1];
    const float* att = (const float*)d_in[2];
    float*       out = (float*)d_out;

    scores_hist_kernel<<<(NEDGE + 255) / 256, 256>>>(h_t, att, ei);  // 1
    scan_kernel<<<SCAN_NBLK, SCAN_BLK>>>();                          // 2
    fill_kernel<<<(NEDGE + 255) / 256, 256>>>(ei);                   // 3
    int blocks = (N_NODES * 32 + 255) / 256;
    node_agg_kernel<<<blocks, 256>>>(h_t, out);                      // 4 (ncu)
}

// round 7
// speedup vs baseline: 1.3326x; 1.3326x over previous
#include <cuda_runtime.h>
#include <cuda_bf16.h>
#include <math.h>

#define N_NODES 50000
#define DIM     64
#define NHEAD   8
#define NEDGE   800000
#define NEG_SLOPE 0.2f

#define SCAN_BLK  1024
#define SCAN_NBLK ((N_NODES + SCAN_BLK - 1) / SCAN_BLK)   // 49

// Scratch (device globals: allocation-free rule).
// INVARIANT: g_deg is zero at module load and re-zeroed by fill_kernel each
// call, so every kernel_launch sees it zeroed.
__device__ float g_sdst[N_NODES * NHEAD];
__device__ float g_ssrc[N_NODES * NHEAD];
__device__ int   g_deg[N_NODES];
__device__ int   g_row[N_NODES + 1];
__device__ int   g_cursor[N_NODES];
__device__ int   g_csr_src[NEDGE];
__device__ float g_csr_ex[(size_t)NEDGE * NHEAD];   // per-edge exp values
__device__ int   g_bsum[SCAN_NBLK];

__device__ __forceinline__ float lrelu(float v) {
    return v >= 0.0f ? v : NEG_SLOPE * v;
}

// ---------------------------------------------------------------------------
// Kernel 1: per-node scores + fused degree histogram (grid = NEDGE threads).
__global__ void scores_hist_kernel(const float* __restrict__ h_t,
                                   const float* __restrict__ att,
                                   const int* __restrict__ ei) {
    __shared__ float s_att[NHEAD * 2 * DIM];
    for (int i = threadIdx.x; i < NHEAD * 2 * DIM; i += blockDim.x)
        s_att[i] = att[i];
    __syncthreads();

    int idx = blockIdx.x * blockDim.x + threadIdx.x;
    if (idx >= NEDGE) return;

    atomicAdd(&g_deg[ei[NEDGE + idx]], 1);   // g_deg pre-zeroed

    int n = idx >> 4;
    int c = idx & 15;
    int h = c & 7;
    bool is_src = (c >= 8);

    const float* arow = s_att + h * (2 * DIM) + (is_src ? DIM : 0);
    const float4* hp = (const float4*)(h_t + (size_t)n * DIM);

    float acc = 0.0f;
#pragma unroll
    for (int k = 0; k < 16; k++) {
        float4 v = hp[k];
        acc += v.x * arow[k * 4 + 0] + v.y * arow[k * 4 + 1]
             + v.z * arow[k * 4 + 2] + v.w * arow[k * 4 + 3];
    }
    if (is_src) g_ssrc[n * NHEAD + h] = acc;
    else        g_sdst[n * NHEAD + h] = acc;
}

// ---------------------------------------------------------------------------
// Kernel 2 (scan A): per-block sums of degrees
__global__ void scanA_kernel() {
    __shared__ int red[32];
    int i = blockIdx.x * SCAN_BLK + threadIdx.x;
    int v = (i < N_NODES) ? g_deg[i] : 0;
#pragma unroll
    for (int o = 16; o > 0; o >>= 1)
        v += __shfl_down_sync(0xffffffffu, v, o);
    if ((threadIdx.x & 31) == 0) red[threadIdx.x >> 5] = v;
    __syncthreads();
    if (threadIdx.x < 32) {
        int w = red[threadIdx.x];
#pragma unroll
        for (int o = 16; o > 0; o >>= 1)
            w += __shfl_down_sync(0xffffffffu, w, o);
        if (threadIdx.x == 0) g_bsum[blockIdx.x] = w;
    }
}

// Kernel 3 (scan C): block offset (warp-reduce prior block sums) + in-block
// exclusive scan -> row/cursor.
__global__ void scanC_kernel() {
    __shared__ int sh[SCAN_BLK];
    __shared__ int s_boff;
    int t = threadIdx.x;

    if (t < 32) {
        int acc = 0;
        for (int b = t; b < blockIdx.x; b += 32) acc += g_bsum[b];
#pragma unroll
        for (int o = 16; o > 0; o >>= 1)
            acc += __shfl_down_sync(0xffffffffu, acc, o);
        if (t == 0) s_boff = acc;
    }

    int i = blockIdx.x * SCAN_BLK + t;
    int d = (i < N_NODES) ? g_deg[i] : 0;
    sh[t] = d;
    __syncthreads();
    for (int o = 1; o < SCAN_BLK; o <<= 1) {
        int u = (t >= o) ? sh[t - o] : 0;
        __syncthreads();
        sh[t] += u;
        __syncthreads();
    }
    if (i < N_NODES) {
        int excl = s_boff + sh[t] - d;
        g_row[i] = excl;
        g_cursor[i] = excl;
    }
    if (i == N_NODES - 1) g_row[N_NODES] = NEDGE;
}

// ---------------------------------------------------------------------------
// Kernel 4: fill CSR + precompute per-edge exp(lrelu(sdst+ssrc)) for all 8
// heads. Also re-zeroes g_deg for the next call.
__global__ void fill_kernel(const int* __restrict__ ei) {
    int e = blockIdx.x * blockDim.x + threadIdx.x;
    if (e < N_NODES) g_deg[e] = 0;
    if (e >= NEDGE) return;
    int src = ei[e];
    int dst = ei[NEDGE + e];
    int p = atomicAdd(&g_cursor[dst], 1);
    g_csr_src[p] = src;

    const float4* pd = (const float4*)(g_sdst + dst * NHEAD);
    const float4* ps = (const float4*)(g_ssrc + src * NHEAD);
    float4 d0 = pd[0], d1 = pd[1];
    float4 s0 = ps[0], s1 = ps[1];
    float4 e0, e1;
    e0.x = __expf(lrelu(d0.x + s0.x));
    e0.y = __expf(lrelu(d0.y + s0.y));
    e0.z = __expf(lrelu(d0.z + s0.z));
    e0.w = __expf(lrelu(d0.w + s0.w));
    e1.x = __expf(lrelu(d1.x + s1.x));
    e1.y = __expf(lrelu(d1.y + s1.y));
    e1.z = __expf(lrelu(d1.z + s1.z));
    e1.w = __expf(lrelu(d1.w + s1.w));
    float4* pe = (float4*)(g_csr_ex + (size_t)p * NHEAD);
    pe[0] = e0;
    pe[1] = e1;
}

// ---------------------------------------------------------------------------
// Kernel 5: aggregation + normalize + ELU. One warp per node.
// lane -> (h = lane>>2, q = lane&3); lane owns float4 slots {2q,2q+1,2q+8,2q+9}
// of each 64-float h_t row, so each LDG.128 stays within ONE 128B line
// (4 distinct 16B slots x 8-lane broadcast) -> 4 wavefronts per edge.
__global__ void node_agg_kernel(const float* __restrict__ h_t,
                                float* __restrict__ out) {
    int warp = (blockIdx.x * blockDim.x + threadIdx.x) >> 5;
    if (warp >= N_NODES) return;
    int lane = threadIdx.x & 31;
    int n = warp;
    int rs = g_row[n];
    int re = g_row[n + 1];

    int h = lane >> 2;
    int q = lane & 3;
    // this lane's float offsets within a row: q*8, q*8+4, 32+q*8, 36+q*8
    int o0 = q * 8, o1 = o0 + 4, o2 = o0 + 32, o3 = o0 + 36;

    float4 a0 = make_float4(0.f, 0.f, 0.f, 0.f);
    float4 a1 = a0, a2 = a0, a3 = a0;
    float denom = 0.0f;

    for (int base = rs; base < re; base += 32) {
        int cnt = re - base; if (cnt > 32) cnt = 32;
        int s = (lane < cnt) ? g_csr_src[base + lane] : 0;

        int j = 0;
        for (; j + 2 <= cnt; j += 2) {
            int s0 = __shfl_sync(0xffffffffu, s, j);
            int s1 = __shfl_sync(0xffffffffu, s, j + 1);
            // ex loads are independent of the shfl (position-indexed)
            float e0 = __ldg(&g_csr_ex[(size_t)(base + j) * NHEAD + h]);
            float e1 = __ldg(&g_csr_ex[(size_t)(base + j + 1) * NHEAD + h]);

            const float* r0 = h_t + (size_t)s0 * DIM;
            const float* r1 = h_t + (size_t)s1 * DIM;
            float4 x00 = *(const float4*)(r0 + o0);
            float4 x01 = *(const float4*)(r0 + o1);
            float4 x02 = *(const float4*)(r0 + o2);
            float4 x03 = *(const float4*)(r0 + o3);
            float4 x10 = *(const float4*)(r1 + o0);
            float4 x11 = *(const float4*)(r1 + o1);
            float4 x12 = *(const float4*)(r1 + o2);
            float4 x13 = *(const float4*)(r1 + o3);

            denom += e0 + e1;

            a0.x += e0*x00.x; a0.y += e0*x00.y; a0.z += e0*x00.z; a0.w += e0*x00.w;
            a1.x += e0*x01.x; a1.y += e0*x01.y; a1.z += e0*x01.z; a1.w += e0*x01.w;
            a2.x += e0*x02.x; a2.y += e0*x02.y; a2.z += e0*x02.z; a2.w += e0*x02.w;
            a3.x += e0*x03.x; a3.y += e0*x03.y; a3.z += e0*x03.z; a3.w += e0*x03.w;

            a0.x += e1*x10.x; a0.y += e1*x10.y; a0.z += e1*x10.z; a0.w += e1*x10.w;
            a1.x += e1*x11.x; a1.y += e1*x11.y; a1.z += e1*x11.z; a1.w += e1*x11.w;
            a2.x += e1*x12.x; a2.y += e1*x12.y; a2.z += e1*x12.z; a2.w += e1*x12.w;
            a3.x += e1*x13.x; a3.y += e1*x13.y; a3.z += e1*x13.z; a3.w += e1*x13.w;
        }
        for (; j < cnt; j++) {
            int sj = __shfl_sync(0xffffffffu, s, j);
            float ex = __ldg(&g_csr_ex[(size_t)(base + j) * NHEAD + h]);
            const float* r = h_t + (size_t)sj * DIM;
            float4 x0 = *(const float4*)(r + o0);
            float4 x1 = *(const float4*)(r + o1);
            float4 x2 = *(const float4*)(r + o2);
            float4 x3 = *(const float4*)(r + o3);
            denom += ex;
            a0.x += ex*x0.x; a0.y += ex*x0.y; a0.z += ex*x0.z; a0.w += ex*x0.w;
            a1.x += ex*x1.x; a1.y += ex*x1.y; a1.z += ex*x1.z; a1.w += ex*x1.w;
            a2.x += ex*x2.x; a2.y += ex*x2.y; a2.z += ex*x2.z; a2.w += ex*x2.w;
            a3.x += ex*x3.x; a3.y += ex*x3.y; a3.z += ex*x3.z; a3.w += ex*x3.w;
        }
    }

    float inv = (re > rs) ? 1.0f / denom : 0.0f;   // zero-degree -> zeros

    float* orow = out + (size_t)n * (NHEAD * DIM) + h * DIM;
    float4 r4[4] = {a0, a1, a2, a3};
    int offs[4] = {o0, o1, o2, o3};
#pragma unroll
    for (int k = 0; k < 4; k++) {
        float4 x = r4[k];
        x.x *= inv; x.y *= inv; x.z *= inv; x.w *= inv;
        x.x = x.x > 0.f ? x.x : expm1f(x.x);
        x.y = x.y > 0.f ? x.y : expm1f(x.y);
        x.z = x.z > 0.f ? x.z : expm1f(x.z);
        x.w = x.w > 0.f ? x.w : expm1f(x.w);
        *(float4*)(orow + offs[k]) = x;
    }
}

// ---------------------------------------------------------------------------
extern "C" void kernel_launch(void* const* d_in, const int* in_sizes, int n_in,
                              void* d_out, int out_size) {
    const float* h_t = (const float*)d_in[0];
    const int*   ei  = (const int*)d_in[1];
    const float* att = (const float*)d_in[2];
    float*       out = (float*)d_out;

    scores_hist_kernel<<<(NEDGE + 255) / 256, 256>>>(h_t, att, ei);  // 1
    scanA_kernel<<<SCAN_NBLK, SCAN_BLK>>>();                         // 2
    scanC_kernel<<<SCAN_NBLK, SCAN_BLK>>>();                         // 3
    fill_kernel<<<(NEDGE + 255) / 256, 256>>>(ei);                   // 4
    int blocks = (N_NODES * 32 + 255) / 256;
    node_agg_kernel<<<blocks, 256>>>(h_t, out);                      // 5
}

// round 8
// speedup vs baseline: 1.8046x; 1.3542x over previous
#include <cuda_runtime.h>
#include <cuda_bf16.h>
#include <math.h>

#define N_NODES 50000
#define DIM     64
#define NHEAD   8
#define NEDGE   800000
#define NEG_SLOPE 0.2f

#define SCAN_BLK  1024
#define SCAN_NBLK ((N_NODES + SCAN_BLK - 1) / SCAN_BLK)   // 49

// Scratch (device globals: allocation-free rule).
// INVARIANT: g_deg is zero at module load and re-zeroed by fill_kernel each
// call, so every kernel_launch sees it zeroed.
__device__ float g_sdst[N_NODES * NHEAD];
__device__ float g_ssrc[N_NODES * NHEAD];
__device__ int   g_deg[N_NODES];
__device__ int   g_row[N_NODES + 1];
__device__ int   g_cursor[N_NODES];
__device__ int   g_csr_src[NEDGE];
__device__ float g_csr_ex[(size_t)NEDGE * NHEAD];   // per-edge exp values

__device__ __forceinline__ float lrelu(float v) {
    return v >= 0.0f ? v : NEG_SLOPE * v;
}

// ---------------------------------------------------------------------------
// Kernel 1: per-node scores (warp computes 2 nodes; h_t read exactly once)
// + fused degree histogram (one edge per thread; grid = NEDGE threads = 25k
// warps = 50k nodes, exact match).
__global__ void scores_hist_kernel(const float* __restrict__ h_t,
                                   const float* __restrict__ att,
                                   const int* __restrict__ ei) {
    __shared__ float s_att[NHEAD * 2 * DIM];   // 1024 floats
    for (int i = threadIdx.x; i < NHEAD * 2 * DIM; i += blockDim.x)
        s_att[i] = att[i];
    __syncthreads();

    int idx = blockIdx.x * blockDim.x + threadIdx.x;
    if (idx >= NEDGE) return;

    atomicAdd(&g_deg[ei[NEDGE + idx]], 1);   // g_deg pre-zeroed

    // ---- scores: warp handles nodes 2w, 2w+1 ----
    int lane = threadIdx.x & 31;
    int half = lane >> 4;            // which of the 2 nodes
    int sub  = lane & 15;            // 16 lanes cover one 64-float row
    int n = (idx >> 5) * 2 + half;

    const float4 x = ((const float4*)(h_t + (size_t)n * DIM))[sub];

    // acc[c]: c&7 = head, c>>3 = is_src  (att[h][0:64]=dst, [64:128]=src)
    float acc[16];
#pragma unroll
    for (int c = 0; c < 16; c++) {
        const float4 a = *(const float4*)(s_att + (c & 7) * 128 + (c >> 3) * 64 + sub * 4);
        acc[c] = x.x * a.x + x.y * a.y + x.z * a.z + x.w * a.w;
    }
    // reduce across the 16 lanes of this half (xor offsets < 16 stay in-half)
#pragma unroll
    for (int o = 8; o > 0; o >>= 1) {
#pragma unroll
        for (int c = 0; c < 16; c++)
            acc[c] += __shfl_xor_sync(0xffffffffu, acc[c], o);
    }
    if (sub == 0) {
        float4* pd = (float4*)(g_sdst + n * NHEAD);
        float4* ps = (float4*)(g_ssrc + n * NHEAD);
        pd[0] = make_float4(acc[0], acc[1], acc[2], acc[3]);
        pd[1] = make_float4(acc[4], acc[5], acc[6], acc[7]);
        ps[0] = make_float4(acc[8], acc[9], acc[10], acc[11]);
        ps[1] = make_float4(acc[12], acc[13], acc[14], acc[15]);
    }
}

// ---------------------------------------------------------------------------
// Kernel 2: single-kernel scan. Each block self-computes its offset by
// strided-summing all preceding degrees (no inter-block dependency), then
// does an in-block exclusive scan of its own chunk.
__global__ void scan_kernel() {
    __shared__ int sh[SCAN_BLK];
    __shared__ int red[32];
    __shared__ int s_boff;
    int t = threadIdx.x;
    int bid = blockIdx.x;

    // block offset = sum(g_deg[0 .. bid*SCAN_BLK))
    int limit = bid * SCAN_BLK;
    int acc = 0;
    for (int i = t; i < limit; i += SCAN_BLK) acc += g_deg[i];
#pragma unroll
    for (int o = 16; o > 0; o >>= 1)
        acc += __shfl_down_sync(0xffffffffu, acc, o);
    if ((t & 31) == 0) red[t >> 5] = acc;
    __syncthreads();
    if (t < 32) {
        int w = red[t];
#pragma unroll
        for (int o = 16; o > 0; o >>= 1)
            w += __shfl_down_sync(0xffffffffu, w, o);
        if (t == 0) s_boff = w;
    }

    // in-block inclusive scan of own chunk
    int i = bid * SCAN_BLK + t;
    int d = (i < N_NODES) ? g_deg[i] : 0;
    sh[t] = d;
    __syncthreads();
    for (int o = 1; o < SCAN_BLK; o <<= 1) {
        int u = (t >= o) ? sh[t - o] : 0;
        __syncthreads();
        sh[t] += u;
        __syncthreads();
    }
    if (i < N_NODES) {
        int excl = s_boff + sh[t] - d;
        g_row[i] = excl;
        g_cursor[i] = excl;
    }
    if (i == N_NODES - 1) g_row[N_NODES] = NEDGE;
}

// ---------------------------------------------------------------------------
// Kernel 3: fill CSR + precompute per-edge exp for all 8 heads; re-zero g_deg.
__global__ void fill_kernel(const int* __restrict__ ei) {
    int e = blockIdx.x * blockDim.x + threadIdx.x;
    if (e < N_NODES) g_deg[e] = 0;
    if (e >= NEDGE) return;
    int src = ei[e];
    int dst = ei[NEDGE + e];
    int p = atomicAdd(&g_cursor[dst], 1);
    g_csr_src[p] = src;

    const float4* pd = (const float4*)(g_sdst + dst * NHEAD);
    const float4* ps = (const float4*)(g_ssrc + src * NHEAD);
    float4 d0 = pd[0], d1 = pd[1];
    float4 s0 = ps[0], s1 = ps[1];
    float4 e0, e1;
    e0.x = __expf(lrelu(d0.x + s0.x));
    e0.y = __expf(lrelu(d0.y + s0.y));
    e0.z = __expf(lrelu(d0.z + s0.z));
    e0.w = __expf(lrelu(d0.w + s0.w));
    e1.x = __expf(lrelu(d1.x + s1.x));
    e1.y = __expf(lrelu(d1.y + s1.y));
    e1.z = __expf(lrelu(d1.z + s1.z));
    e1.w = __expf(lrelu(d1.w + s1.w));
    float4* pe = (float4*)(g_csr_ex + (size_t)p * NHEAD);
    pe[0] = e0;
    pe[1] = e1;
}

// ---------------------------------------------------------------------------
// Kernel 4 (ncu-profiled): aggregation + normalize + ELU. One warp per node.
// lane (h = lane>>2, q = lane&3) owns float4 slots {2q,2q+1,2q+8,2q+9} so each
// LDG.128 touches ONE 128B line (4 wavefronts/edge). 128-thread blocks cut
// degree-variance straggler loss.
__global__ void __launch_bounds__(128, 8)
node_agg_kernel(const float* __restrict__ h_t, float* __restrict__ out) {
    int warp = (blockIdx.x * blockDim.x + threadIdx.x) >> 5;
    if (warp >= N_NODES) return;
    int lane = threadIdx.x & 31;
    int n = warp;
    int rs = g_row[n];
    int re = g_row[n + 1];

    int h = lane >> 2;
    int q = lane & 3;
    int o0 = q * 8, o1 = o0 + 4, o2 = o0 + 32, o3 = o0 + 36;

    float4 a0 = make_float4(0.f, 0.f, 0.f, 0.f);
    float4 a1 = a0, a2 = a0, a3 = a0;
    float denom = 0.0f;

    for (int base = rs; base < re; base += 32) {
        int cnt = re - base; if (cnt > 32) cnt = 32;
        int s = (lane < cnt) ? g_csr_src[base + lane] : 0;

        int j = 0;
        for (; j + 2 <= cnt; j += 2) {
            int s0 = __shfl_sync(0xffffffffu, s, j);
            int s1 = __shfl_sync(0xffffffffu, s, j + 1);
            float e0 = __ldg(&g_csr_ex[(size_t)(base + j) * NHEAD + h]);
            float e1 = __ldg(&g_csr_ex[(size_t)(base + j + 1) * NHEAD + h]);

            const float* r0 = h_t + (size_t)s0 * DIM;
            const float* r1 = h_t + (size_t)s1 * DIM;
            float4 x00 = *(const float4*)(r0 + o0);
            float4 x01 = *(const float4*)(r0 + o1);
            float4 x02 = *(const float4*)(r0 + o2);
            float4 x03 = *(const float4*)(r0 + o3);
            float4 x10 = *(const float4*)(r1 + o0);
            float4 x11 = *(const float4*)(r1 + o1);
            float4 x12 = *(const float4*)(r1 + o2);
            float4 x13 = *(const float4*)(r1 + o3);

            denom += e0 + e1;

            a0.x += e0*x00.x; a0.y += e0*x00.y; a0.z += e0*x00.z; a0.w += e0*x00.w;
            a1.x += e0*x01.x; a1.y += e0*x01.y; a1.z += e0*x01.z; a1.w += e0*x01.w;
            a2.x += e0*x02.x; a2.y += e0*x02.y; a2.z += e0*x02.z; a2.w += e0*x02.w;
            a3.x += e0*x03.x; a3.y += e0*x03.y; a3.z += e0*x03.z; a3.w += e0*x03.w;

            a0.x += e1*x10.x; a0.y += e1*x10.y; a0.z += e1*x10.z; a0.w += e1*x10.w;
            a1.x += e1*x11.x; a1.y += e1*x11.y; a1.z += e1*x11.z; a1.w += e1*x11.w;
            a2.x += e1*x12.x; a2.y += e1*x12.y; a2.z += e1*x12.z; a2.w += e1*x12.w;
            a3.x += e1*x13.x; a3.y += e1*x13.y; a3.z += e1*x13.z; a3.w += e1*x13.w;
        }
        for (; j < cnt; j++) {
            int sj = __shfl_sync(0xffffffffu, s, j);
            float ex = __ldg(&g_csr_ex[(size_t)(base + j) * NHEAD + h]);
            const float* r = h_t + (size_t)sj * DIM;
            float4 x0 = *(const float4*)(r + o0);
            float4 x1 = *(const float4*)(r + o1);
            float4 x2 = *(const float4*)(r + o2);
            float4 x3 = *(const float4*)(r + o3);
            denom += ex;
            a0.x += ex*x0.x; a0.y += ex*x0.y; a0.z += ex*x0.z; a0.w += ex*x0.w;
            a1.x += ex*x1.x; a1.y += ex*x1.y; a1.z += ex*x1.z; a1.w += ex*x1.w;
            a2.x += ex*x2.x; a2.y += ex*x2.y; a2.z += ex*x2.z; a2.w += ex*x2.w;
            a3.x += ex*x3.x; a3.y += ex*x3.y; a3.z += ex*x3.z; a3.w += ex*x3.w;
        }
    }

    float inv = (re > rs) ? 1.0f / denom : 0.0f;   // zero-degree -> zeros

    float* orow = out + (size_t)n * (NHEAD * DIM) + h * DIM;
    float4 r4[4] = {a0, a1, a2, a3};
    int offs[4] = {o0, o1, o2, o3};
#pragma unroll
    for (int k = 0; k < 4; k++) {
        float4 x = r4[k];
        x.x *= inv; x.y *= inv; x.z *= inv; x.w *= inv;
        x.x = x.x > 0.f ? x.x : expm1f(x.x);
        x.y = x.y > 0.f ? x.y : expm1f(x.y);
        x.z = x.z > 0.f ? x.z : expm1f(x.z);
        x.w = x.w > 0.f ? x.w : expm1f(x.w);
        *(float4*)(orow + offs[k]) = x;
    }
}

// ---------------------------------------------------------------------------
extern "C" void kernel_launch(void* const* d_in, const int* in_sizes, int n_in,
                              void* d_out, int out_size) {
    const float* h_t = (const float*)d_in[0];
    const int*   ei  = (const int*)d_in[1];
    const float* att = (const float*)d_in[2];
    float*       out = (float*)d_out;

    scores_hist_kernel<<<(NEDGE + 255) / 256, 256>>>(h_t, att, ei);  // 1
    scan_kernel<<<SCAN_NBLK, SCAN_BLK>>>();                          // 2
    fill_kernel<<<(NEDGE + 255) / 256, 256>>>(ei);                   // 3
    int blocks = (N_NODES * 32 + 127) / 128;
    node_agg_kernel<<<blocks, 128>>>(h_t, out);                      // 4 (ncu)
}